// round 1
// baseline (speedup 1.0000x reference)
#include <cuda_runtime.h>

#define B_   16
#define C_   64
#define H_   64
#define W_   64
#define N_   4096
#define M_   1024
#define D8   8
#define D2   32
#define CH48 48

// Device scratch (no cudaMalloc allowed)
__device__ float d_tmp[B_ * CH48 * N_];   // theta(0..7) | phi_pre(8..15) | g_pre(16..47), full res
__device__ float d_phi[B_ * D8 * M_];     // pooled phi
__device__ float d_g[B_ * D2 * M_];       // pooled g

// ---------------------------------------------------------------------------
// P1: fused 1x1 conv producing 48 channels (theta, phi_pre, g_pre) at full res
// ---------------------------------------------------------------------------
__global__ void __launch_bounds__(256) conv48_kernel(
    const float* __restrict__ x,
    const float* __restrict__ w_theta, const float* __restrict__ b_theta,
    const float* __restrict__ w_phi,   const float* __restrict__ b_phi,
    const float* __restrict__ w_g,     const float* __restrict__ b_g)
{
    __shared__ float w_s[C_ * CH48];   // transposed: w_s[c][ch]
    __shared__ float bias_s[CH48];
    int tid = threadIdx.x;
    for (int i = tid; i < C_ * CH48; i += 256) {
        int c = i / CH48, ch = i % CH48;
        float v;
        if (ch < 8)       v = w_theta[ch * C_ + c];
        else if (ch < 16) v = w_phi[(ch - 8) * C_ + c];
        else              v = w_g[(ch - 16) * C_ + c];
        w_s[i] = v;
    }
    if (tid < CH48) {
        bias_s[tid] = (tid < 8) ? b_theta[tid]
                    : (tid < 16 ? b_phi[tid - 8] : b_g[tid - 16]);
    }
    __syncthreads();

    int idx = blockIdx.x * 256 + tid;
    int b = idx >> 12;
    int n = idx & (N_ - 1);

    float acc[CH48];
    #pragma unroll
    for (int ch = 0; ch < CH48; ch++) acc[ch] = bias_s[ch];

    const float* xb = x + ((size_t)b * C_) * N_ + n;
    #pragma unroll 4
    for (int c = 0; c < C_; c++) {
        float xv = xb[(size_t)c * N_];
        const float4* wrow = (const float4*)(w_s + c * CH48);
        #pragma unroll
        for (int j = 0; j < CH48 / 4; j++) {
            float4 w4 = wrow[j];
            acc[4 * j + 0] += w4.x * xv;
            acc[4 * j + 1] += w4.y * xv;
            acc[4 * j + 2] += w4.z * xv;
            acc[4 * j + 3] += w4.w * xv;
        }
    }
    float* tb = d_tmp + ((size_t)b * CH48) * N_ + n;
    #pragma unroll
    for (int ch = 0; ch < CH48; ch++) tb[(size_t)ch * N_] = acc[ch];
}

// ---------------------------------------------------------------------------
// P2: 2x2 maxpool of channels 8..47 of d_tmp -> d_phi / d_g
// ---------------------------------------------------------------------------
__global__ void __launch_bounds__(256) pool_kernel()
{
    int idx = blockIdx.x * 256 + threadIdx.x;   // B * 40 * 1024 total
    int b  = idx / (40 * M_);
    int r  = idx % (40 * M_);
    int ch = r / M_;
    int m  = r % M_;
    int mh = m >> 5, mw = m & 31;

    const float* src = d_tmp + ((size_t)b * CH48 + 8 + ch) * N_;
    int base0 = (2 * mh) * W_ + 2 * mw;
    float2 a  = *(const float2*)(src + base0);
    float2 bb = *(const float2*)(src + base0 + W_);
    float v = fmaxf(fmaxf(a.x, a.y), fmaxf(bb.x, bb.y));

    if (ch < 8) d_phi[((size_t)b * D8 + ch) * M_ + m] = v;
    else        d_g[((size_t)b * D2 + (ch - 8)) * M_ + m] = v;
}

// ---------------------------------------------------------------------------
// Main fused attention kernel
// One CTA = (batch b, tile of 128 queries). phi + g resident in smem.
// Each warp processes query pairs: logits (32/lane) -> softmax -> PV with
// per-lane partial channel accumulators -> padded smem transpose-reduce ->
// AG staged in smem -> coalesced w_o projection + residual epilogue.
// ---------------------------------------------------------------------------
#define SM_PHI 0
#define SM_G   (D8 * M_)                  // 8192
#define SM_RED (SM_G + D2 * M_)           // 40960
#define SM_AG  (SM_RED + 8 * 32 * 33)     // 49408
#define SM_WO  (SM_AG + 128 * 36)         // 54016
#define SM_BO  (SM_WO + 64 * 32)          // 56064
#define SM_TOT (SM_BO + 64)               // 56128 floats = 224512 bytes

__global__ void __launch_bounds__(256, 1) attn_main_kernel(
    const float* __restrict__ x,
    const float* __restrict__ w_o,
    const float* __restrict__ b_o,
    const float* __restrict__ sigma,
    float* __restrict__ out)
{
    extern __shared__ float sm[];
    float* phi_s = sm + SM_PHI;
    float* g_s   = sm + SM_G;
    float* red   = sm + SM_RED;
    float* ag_s  = sm + SM_AG;
    float* wo_s  = sm + SM_WO;
    float* bo_s  = sm + SM_BO;

    int tid   = threadIdx.x;
    int b     = blockIdx.y;
    int qbase = blockIdx.x * 128;

    // Cooperative loads: phi (32KB), g (128KB), w_o (8KB), b_o
    {
        const float4* p4 = (const float4*)(d_phi + (size_t)b * D8 * M_);
        float4* s4 = (float4*)phi_s;
        for (int i = tid; i < D8 * M_ / 4; i += 256) s4[i] = p4[i];
        const float4* g4 = (const float4*)(d_g + (size_t)b * D2 * M_);
        float4* gs4 = (float4*)g_s;
        for (int i = tid; i < D2 * M_ / 4; i += 256) gs4[i] = g4[i];
        const float4* w4 = (const float4*)w_o;
        float4* ws4 = (float4*)wo_s;
        for (int i = tid; i < 64 * 32 / 4; i += 256) ws4[i] = w4[i];
        if (tid < 64) bo_s[tid] = b_o[tid];
    }
    __syncthreads();

    int warp = tid >> 5, lane = tid & 31;
    float* myred = red + warp * (32 * 33);
    const float* th_base = d_tmp + (size_t)b * CH48 * N_;

    #pragma unroll 1
    for (int pr = 0; pr < 8; pr++) {
        int l0 = warp * 16 + pr * 2;       // local query index (pair)
        int n0 = qbase + l0;

        float th0[8], th1[8];
        #pragma unroll
        for (int d = 0; d < 8; d++) {
            th0[d] = th_base[(size_t)d * N_ + n0];
            th1[d] = th_base[(size_t)d * N_ + n0 + 1];
        }

        // Logits: lane handles m = j*32 + lane (conflict-free phi access)
        float pA[32], pB[32];
        #pragma unroll
        for (int j = 0; j < 32; j++) {
            int m = j * 32 + lane;
            float s0 = 0.f, s1 = 0.f;
            #pragma unroll
            for (int d = 0; d < 8; d++) {
                float pv = phi_s[d * M_ + m];
                s0 += th0[d] * pv;
                s1 += th1[d] * pv;
            }
            pA[j] = s0; pB[j] = s1;
        }

        // Softmax (full row in registers; no online pass needed)
        float mx0 = pA[0], mx1 = pB[0];
        #pragma unroll
        for (int j = 1; j < 32; j++) { mx0 = fmaxf(mx0, pA[j]); mx1 = fmaxf(mx1, pB[j]); }
        #pragma unroll
        for (int o = 16; o; o >>= 1) {
            mx0 = fmaxf(mx0, __shfl_xor_sync(0xffffffffu, mx0, o));
            mx1 = fmaxf(mx1, __shfl_xor_sync(0xffffffffu, mx1, o));
        }
        float r0 = 0.f, r1 = 0.f;
        #pragma unroll
        for (int j = 0; j < 32; j++) {
            pA[j] = __expf(pA[j] - mx0); r0 += pA[j];
            pB[j] = __expf(pB[j] - mx1); r1 += pB[j];
        }
        #pragma unroll
        for (int o = 16; o; o >>= 1) {
            r0 += __shfl_xor_sync(0xffffffffu, r0, o);
            r1 += __shfl_xor_sync(0xffffffffu, r1, o);
        }
        float inv0 = 1.f / r0, inv1 = 1.f / r1;

        // PV: two queries share each g read (halves smem traffic)
        float accA[32], accB[32];
        #pragma unroll
        for (int c = 0; c < 32; c++) { accA[c] = 0.f; accB[c] = 0.f; }
        #pragma unroll
        for (int j = 0; j < 32; j++) {
            int m = j * 32 + lane;
            float pa = pA[j], pb = pB[j];
            #pragma unroll
            for (int c = 0; c < 32; c++) {
                float gv = g_s[c * M_ + m];     // lanes vary m: conflict-free
                accA[c] += pa * gv;
                accB[c] += pb * gv;
            }
        }

        // Cross-lane reduce via padded smem transpose (row pad 33: conflict-free)
        #pragma unroll
        for (int c = 0; c < 32; c++) myred[c * 33 + lane] = accA[c];
        __syncwarp();
        float vA = 0.f;
        #pragma unroll
        for (int i = 0; i < 32; i++) vA += myred[lane * 33 + i];
        __syncwarp();
        #pragma unroll
        for (int c = 0; c < 32; c++) myred[c * 33 + lane] = accB[c];
        __syncwarp();
        float vB = 0.f;
        #pragma unroll
        for (int i = 0; i < 32; i++) vB += myred[lane * 33 + i];
        __syncwarp();

        ag_s[l0 * 36 + lane]       = vA * inv0;   // AG[q][c=lane], pad 36 keeps f4 align
        ag_s[(l0 + 1) * 36 + lane] = vB * inv1;
    }
    __syncthreads();

    // Epilogue: out[b,k,qbase+nl] = x + sigma*(b_o[k] + sum_c w_o[k,c]*AG[nl,c])
    float sig = sigma[0];
    int nl = tid & 127;
    int kh = tid >> 7;

    float ag[32];
    #pragma unroll
    for (int c4 = 0; c4 < 8; c4++) {
        float4 v = *(const float4*)(ag_s + nl * 36 + 4 * c4);
        ag[4 * c4 + 0] = v.x; ag[4 * c4 + 1] = v.y;
        ag[4 * c4 + 2] = v.z; ag[4 * c4 + 3] = v.w;
    }
    size_t xoff_base = ((size_t)b * C_ + kh * 32) * N_ + qbase + nl;
    #pragma unroll 4
    for (int kk = 0; kk < 32; kk++) {
        int k = kh * 32 + kk;
        float val = bo_s[k];
        const float4* wrow = (const float4*)(wo_s + k * 32);
        #pragma unroll
        for (int c4 = 0; c4 < 8; c4++) {
            float4 w4 = wrow[c4];
            val += w4.x * ag[4 * c4] + w4.y * ag[4 * c4 + 1]
                 + w4.z * ag[4 * c4 + 2] + w4.w * ag[4 * c4 + 3];
        }
        size_t off = xoff_base + (size_t)kk * N_;
        out[off] = x[off] + sig * val;      // coalesced read + write
    }
}

// ---------------------------------------------------------------------------
extern "C" void kernel_launch(void* const* d_in, const int* in_sizes, int n_in,
                              void* d_out, int out_size)
{
    const float* x       = (const float*)d_in[0];
    const float* w_theta = (const float*)d_in[1];
    const float* b_theta = (const float*)d_in[2];
    const float* w_phi   = (const float*)d_in[3];
    const float* b_phi   = (const float*)d_in[4];
    const float* w_g     = (const float*)d_in[5];
    const float* b_g     = (const float*)d_in[6];
    const float* w_o     = (const float*)d_in[7];
    const float* b_o     = (const float*)d_in[8];
    const float* sigma   = (const float*)d_in[9];
    float* out = (float*)d_out;

    conv48_kernel<<<B_ * N_ / 256, 256>>>(x, w_theta, b_theta, w_phi, b_phi, w_g, b_g);
    pool_kernel<<<B_ * 40 * M_ / 256, 256>>>();

    const int smem_bytes = SM_TOT * 4;   // 224512 B
    cudaFuncSetAttribute(attn_main_kernel,
                         cudaFuncAttributeMaxDynamicSharedMemorySize, smem_bytes);
    attn_main_kernel<<<dim3(N_ / 128, B_), 256, smem_bytes>>>(x, w_o, b_o, sigma, out);
}

// round 2
// speedup vs baseline: 1.0551x; 1.0551x over previous
#include <cuda_runtime.h>
#include <cuda_bf16.h>
#include <cstdint>

#define B_   16
#define C_   64
#define H_   64
#define W_   64
#define N_   4096
#define M_   1024
#define D8   8
#define D2   32
#define CH48 48

// Device scratch (no cudaMalloc allowed)
__device__ float d_tmp[B_ * CH48 * N_];   // theta(0..7) | phi_pre(8..15) | g_pre(16..47)
__device__ float d_phi[B_ * D8 * M_];     // pooled phi
__device__ float d_g[B_ * D2 * M_];       // pooled g

// ---- f32x2 packed helpers (sm_100+ PTX; doubles FFMA throughput) -----------
__device__ __forceinline__ void ffma2(unsigned long long& d,
                                      unsigned long long a,
                                      unsigned long long b) {
    asm("fma.rn.f32x2 %0, %1, %2, %0;" : "+l"(d) : "l"(a), "l"(b));
}
__device__ __forceinline__ unsigned long long pack_rr(uint32_t lo, uint32_t hi) {
    unsigned long long r;
    asm("mov.b64 %0, {%1,%2};" : "=l"(r) : "r"(lo), "r"(hi));
    return r;
}
__device__ __forceinline__ unsigned long long pack_ff(float lo, float hi) {
    unsigned long long r;
    asm("mov.b64 %0, {%1,%2};" : "=l"(r) : "f"(lo), "f"(hi));
    return r;
}
__device__ __forceinline__ void unpack_ff(unsigned long long v, float& lo, float& hi) {
    asm("mov.b64 {%0,%1}, %2;" : "=f"(lo), "=f"(hi) : "l"(v));
}

// ---------------------------------------------------------------------------
// P1: fused 1x1 conv producing 48 channels at full res (FFMA2 version)
// ---------------------------------------------------------------------------
__global__ void __launch_bounds__(256) conv48_kernel(
    const float* __restrict__ x,
    const float* __restrict__ w_theta, const float* __restrict__ b_theta,
    const float* __restrict__ w_phi,   const float* __restrict__ b_phi,
    const float* __restrict__ w_g,     const float* __restrict__ b_g)
{
    __shared__ float w_s[C_ * CH48];   // transposed: w_s[c][ch]
    __shared__ float bias_s[CH48];
    int tid = threadIdx.x;
    for (int i = tid; i < C_ * CH48; i += 256) {
        int c = i / CH48, ch = i % CH48;
        float v;
        if (ch < 8)       v = w_theta[ch * C_ + c];
        else if (ch < 16) v = w_phi[(ch - 8) * C_ + c];
        else              v = w_g[(ch - 16) * C_ + c];
        w_s[i] = v;
    }
    if (tid < CH48) {
        bias_s[tid] = (tid < 8) ? b_theta[tid]
                    : (tid < 16 ? b_phi[tid - 8] : b_g[tid - 16]);
    }
    __syncthreads();

    int idx = blockIdx.x * 256 + tid;
    int b = idx >> 12;
    int n = idx & (N_ - 1);

    unsigned long long acc2[24];
    #pragma unroll
    for (int j = 0; j < 24; j++) acc2[j] = pack_ff(bias_s[2 * j], bias_s[2 * j + 1]);

    const float* xb = x + ((size_t)b * C_) * N_ + n;
    #pragma unroll 8
    for (int c = 0; c < C_; c++) {
        float xv = xb[(size_t)c * N_];
        unsigned long long xv2 = pack_ff(xv, xv);
        const float4* wrow = (const float4*)(w_s + c * CH48);
        #pragma unroll
        for (int j = 0; j < 12; j++) {
            float4 w4 = wrow[j];
            ffma2(acc2[2 * j],     xv2, pack_ff(w4.x, w4.y));
            ffma2(acc2[2 * j + 1], xv2, pack_ff(w4.z, w4.w));
        }
    }
    float* tb = d_tmp + ((size_t)b * CH48) * N_ + n;
    #pragma unroll
    for (int j = 0; j < 24; j++) {
        float lo, hi;
        unpack_ff(acc2[j], lo, hi);
        tb[(size_t)(2 * j) * N_]     = lo;
        tb[(size_t)(2 * j + 1) * N_] = hi;
    }
}

// ---------------------------------------------------------------------------
// P2: 2x2 maxpool of channels 8..47 of d_tmp -> d_phi / d_g
// ---------------------------------------------------------------------------
__global__ void __launch_bounds__(256) pool_kernel()
{
    int idx = blockIdx.x * 256 + threadIdx.x;   // B * 40 * 1024 total
    int b  = idx / (40 * M_);
    int r  = idx % (40 * M_);
    int ch = r / M_;
    int m  = r % M_;
    int mh = m >> 5, mw = m & 31;

    const float* src = d_tmp + ((size_t)b * CH48 + 8 + ch) * N_;
    int base0 = (2 * mh) * W_ + 2 * mw;
    float2 a  = *(const float2*)(src + base0);
    float2 bb = *(const float2*)(src + base0 + W_);
    float v = fmaxf(fmaxf(a.x, a.y), fmaxf(bb.x, bb.y));

    if (ch < 8) d_phi[((size_t)b * D8 + ch) * M_ + m] = v;
    else        d_g[((size_t)b * D2 + (ch - 8)) * M_ + m] = v;
}

// ---------------------------------------------------------------------------
// Main fused attention kernel.
// One CTA = (batch, 128-query tile). phi fp32 + g bf16x2 resident in smem.
// g layout: u32 word per (m, channel-pair cp), index m*17+cp  -> stride 17
// words is coprime with 32 banks => conflict-free when lanes vary m.
// PV inner loop: bf16x2 LDS -> 2x f32x2 FFMA (2 queries) per channel-pair.
// ---------------------------------------------------------------------------
#define GSTR   17
#define SM_PHI 0
#define SM_G   (D8 * M_)                    // 8192   (g2: 1024*17 u32 = 17408)
#define SM_RED (SM_G + M_ * GSTR)           // 25600
#define SM_AG  (SM_RED + 8 * 32 * 33)       // 34048
#define SM_WO  (SM_AG + 128 * 36)           // 38656
#define SM_BO  (SM_WO + 64 * 32)            // 40704
#define SM_TOT (SM_BO + 64)                 // 40768 floats = 163072 B

__global__ void __launch_bounds__(256, 1) attn_main_kernel(
    const float* __restrict__ x,
    const float* __restrict__ w_o,
    const float* __restrict__ b_o,
    const float* __restrict__ sigma,
    float* __restrict__ out)
{
    extern __shared__ float sm[];
    float*    phi_s = sm + SM_PHI;
    uint32_t* g2s   = (uint32_t*)(sm + SM_G);
    float*    red   = sm + SM_RED;
    float*    ag_s  = sm + SM_AG;
    float*    wo_s  = sm + SM_WO;
    float*    bo_s  = sm + SM_BO;

    int tid   = threadIdx.x;
    int b     = blockIdx.y;
    int qbase = blockIdx.x * 128;

    // Cooperative loads
    {
        const float4* p4 = (const float4*)(d_phi + (size_t)b * D8 * M_);
        float4* s4 = (float4*)phi_s;
        for (int i = tid; i < D8 * M_ / 4; i += 256) s4[i] = p4[i];

        const float* gsrc = d_g + (size_t)b * D2 * M_;
        for (int i = tid; i < 16 * M_; i += 256) {       // 16 channel-pairs
            int cp = i >> 10;
            int m  = i & (M_ - 1);
            float v0 = gsrc[(size_t)(2 * cp) * M_ + m];
            float v1 = gsrc[(size_t)(2 * cp + 1) * M_ + m];
            __nv_bfloat162 h = __floats2bfloat162_rn(v0, v1);  // x=v0(lo), y=v1(hi)
            g2s[m * GSTR + cp] = *(uint32_t*)&h;
        }
        const float4* w4 = (const float4*)w_o;
        float4* ws4 = (float4*)wo_s;
        for (int i = tid; i < 64 * 32 / 4; i += 256) ws4[i] = w4[i];
        if (tid < 64) bo_s[tid] = b_o[tid];
    }
    __syncthreads();

    int warp = tid >> 5, lane = tid & 31;
    float* myred = red + warp * (32 * 33);
    const float* th_base = d_tmp + (size_t)b * CH48 * N_;

    #pragma unroll 1
    for (int pr = 0; pr < 8; pr++) {
        int l0 = warp * 16 + pr * 2;       // local query index (pair)
        int n0 = qbase + l0;

        float th0[8], th1[8];
        #pragma unroll
        for (int d = 0; d < 8; d++) {
            th0[d] = th_base[(size_t)d * N_ + n0];
            th1[d] = th_base[(size_t)d * N_ + n0 + 1];
        }

        // Logits: lane handles m = j*32 + lane
        float pA[32], pB[32];
        #pragma unroll
        for (int j = 0; j < 32; j++) {
            int m = j * 32 + lane;
            float s0 = 0.f, s1 = 0.f;
            #pragma unroll
            for (int d = 0; d < 8; d++) {
                float pv = phi_s[d * M_ + m];
                s0 += th0[d] * pv;
                s1 += th1[d] * pv;
            }
            pA[j] = s0; pB[j] = s1;
        }

        // Softmax (full row resident in registers)
        float mx0 = pA[0], mx1 = pB[0];
        #pragma unroll
        for (int j = 1; j < 32; j++) { mx0 = fmaxf(mx0, pA[j]); mx1 = fmaxf(mx1, pB[j]); }
        #pragma unroll
        for (int o = 16; o; o >>= 1) {
            mx0 = fmaxf(mx0, __shfl_xor_sync(0xffffffffu, mx0, o));
            mx1 = fmaxf(mx1, __shfl_xor_sync(0xffffffffu, mx1, o));
        }
        float r0 = 0.f, r1 = 0.f;
        #pragma unroll
        for (int j = 0; j < 32; j++) {
            pA[j] = __expf(pA[j] - mx0); r0 += pA[j];
            pB[j] = __expf(pB[j] - mx1); r1 += pB[j];
        }
        #pragma unroll
        for (int o = 16; o; o >>= 1) {
            r0 += __shfl_xor_sync(0xffffffffu, r0, o);
            r1 += __shfl_xor_sync(0xffffffffu, r1, o);
        }
        float inv0 = 1.f / r0, inv1 = 1.f / r1;

        // PV: bf16x2 g, f32x2 FMA, 2 queries share every g load
        unsigned long long accA2[16], accB2[16];
        #pragma unroll
        for (int cp = 0; cp < 16; cp++) { accA2[cp] = 0ull; accB2[cp] = 0ull; }

        #pragma unroll
        for (int j = 0; j < 32; j++) {
            int m = j * 32 + lane;
            const uint32_t* grow = g2s + m * GSTR;
            unsigned long long pa2 = pack_ff(pA[j], pA[j]);
            unsigned long long pb2 = pack_ff(pB[j], pB[j]);
            #pragma unroll
            for (int cp = 0; cp < 16; cp++) {
                uint32_t u  = grow[cp];
                uint32_t lo = u << 16;
                uint32_t hi = u & 0xffff0000u;
                unsigned long long g64 = pack_rr(lo, hi);
                ffma2(accA2[cp], pa2, g64);
                ffma2(accB2[cp], pb2, g64);
            }
        }

        // Cross-lane reduce via padded smem transpose
        #pragma unroll
        for (int cp = 0; cp < 16; cp++) {
            float lo, hi;
            unpack_ff(accA2[cp], lo, hi);
            myred[(2 * cp) * 33 + lane]     = lo;
            myred[(2 * cp + 1) * 33 + lane] = hi;
        }
        __syncwarp();
        float vA = 0.f;
        #pragma unroll
        for (int i = 0; i < 32; i++) vA += myred[lane * 33 + i];
        __syncwarp();
        #pragma unroll
        for (int cp = 0; cp < 16; cp++) {
            float lo, hi;
            unpack_ff(accB2[cp], lo, hi);
            myred[(2 * cp) * 33 + lane]     = lo;
            myred[(2 * cp + 1) * 33 + lane] = hi;
        }
        __syncwarp();
        float vB = 0.f;
        #pragma unroll
        for (int i = 0; i < 32; i++) vB += myred[lane * 33 + i];
        __syncwarp();

        ag_s[l0 * 36 + lane]       = vA * inv0;   // AG[q][c=lane]
        ag_s[(l0 + 1) * 36 + lane] = vB * inv1;
    }
    __syncthreads();

    // Epilogue: out[b,k,qbase+nl] = x + sigma*(b_o[k] + sum_c w_o[k,c]*AG[nl,c])
    float sig = sigma[0];
    int nl = tid & 127;
    int kh = tid >> 7;

    float ag[32];
    #pragma unroll
    for (int c4 = 0; c4 < 8; c4++) {
        float4 v = *(const float4*)(ag_s + nl * 36 + 4 * c4);
        ag[4 * c4 + 0] = v.x; ag[4 * c4 + 1] = v.y;
        ag[4 * c4 + 2] = v.z; ag[4 * c4 + 3] = v.w;
    }
    size_t xoff_base = ((size_t)b * C_ + kh * 32) * N_ + qbase + nl;
    #pragma unroll 4
    for (int kk = 0; kk < 32; kk++) {
        int k = kh * 32 + kk;
        float val = bo_s[k];
        const float4* wrow = (const float4*)(wo_s + k * 32);
        #pragma unroll
        for (int c4 = 0; c4 < 8; c4++) {
            float4 w4 = wrow[c4];
            val += w4.x * ag[4 * c4] + w4.y * ag[4 * c4 + 1]
                 + w4.z * ag[4 * c4 + 2] + w4.w * ag[4 * c4 + 3];
        }
        size_t off = xoff_base + (size_t)kk * N_;
        out[off] = x[off] + sig * val;
    }
}

// ---------------------------------------------------------------------------
extern "C" void kernel_launch(void* const* d_in, const int* in_sizes, int n_in,
                              void* d_out, int out_size)
{
    const float* x       = (const float*)d_in[0];
    const float* w_theta = (const float*)d_in[1];
    const float* b_theta = (const float*)d_in[2];
    const float* w_phi   = (const float*)d_in[3];
    const float* b_phi   = (const float*)d_in[4];
    const float* w_g     = (const float*)d_in[5];
    const float* b_g     = (const float*)d_in[6];
    const float* w_o     = (const float*)d_in[7];
    const float* b_o     = (const float*)d_in[8];
    const float* sigma   = (const float*)d_in[9];
    float* out = (float*)d_out;

    conv48_kernel<<<B_ * N_ / 256, 256>>>(x, w_theta, b_theta, w_phi, b_phi, w_g, b_g);
    pool_kernel<<<B_ * 40 * M_ / 256, 256>>>();

    const int smem_bytes = SM_TOT * 4;   // 163072 B
    cudaFuncSetAttribute(attn_main_kernel,
                         cudaFuncAttributeMaxDynamicSharedMemorySize, smem_bytes);
    attn_main_kernel<<<dim3(N_ / 128, B_), 256, smem_bytes>>>(x, w_o, b_o, sigma, out);
}

// round 4
// speedup vs baseline: 1.8096x; 1.7152x over previous
#include <cuda_runtime.h>
#include <cuda_bf16.h>
#include <cstdint>

#define B_   16
#define C_   64
#define H_   64
#define W_   64
#define N_   4096
#define M_   1024
#define D8   8
#define D2   32
#define CH48 48

// Device scratch (no cudaMalloc allowed)
__device__ float d_tmp[B_ * CH48 * N_];   // theta(0..7) | phi_pre | g_pre
__device__ float d_phi[B_ * D8 * M_];     // pooled phi (f32)
__device__ float d_g[B_ * D2 * M_];       // pooled g   (f32)

// ---- f32x2 packed helpers ---------------------------------------------------
__device__ __forceinline__ void ffma2(unsigned long long& d,
                                      unsigned long long a,
                                      unsigned long long b) {
    asm("fma.rn.f32x2 %0, %1, %2, %0;" : "+l"(d) : "l"(a), "l"(b));
}
__device__ __forceinline__ unsigned long long pack_ff(float lo, float hi) {
    unsigned long long r;
    asm("mov.b64 %0, {%1,%2};" : "=l"(r) : "f"(lo), "f"(hi));
    return r;
}
__device__ __forceinline__ void unpack_ff(unsigned long long v, float& lo, float& hi) {
    asm("mov.b64 {%0,%1}, %2;" : "=f"(lo), "=f"(hi) : "l"(v));
}

// ---- mma.sync m16n8k16 bf16 (baseline PTX, works on plain sm_103) -----------
__device__ __forceinline__ void mma16816(float& d0, float& d1, float& d2, float& d3,
                                         uint32_t a0, uint32_t a1, uint32_t a2, uint32_t a3,
                                         uint32_t b0, uint32_t b1) {
    asm volatile(
        "mma.sync.aligned.m16n8k16.row.col.f32.bf16.bf16.f32 "
        "{%0,%1,%2,%3}, {%4,%5,%6,%7}, {%8,%9}, {%0,%1,%2,%3};"
        : "+f"(d0), "+f"(d1), "+f"(d2), "+f"(d3)
        : "r"(a0), "r"(a1), "r"(a2), "r"(a3), "r"(b0), "r"(b1));
}

// ---------------------------------------------------------------------------
// P1: fused 1x1 conv producing 48 channels at full res (proven)
// ---------------------------------------------------------------------------
__global__ void __launch_bounds__(256) conv48_kernel(
    const float* __restrict__ x,
    const float* __restrict__ w_theta, const float* __restrict__ b_theta,
    const float* __restrict__ w_phi,   const float* __restrict__ b_phi,
    const float* __restrict__ w_g,     const float* __restrict__ b_g)
{
    __shared__ float w_s[C_ * CH48];
    __shared__ float bias_s[CH48];
    int tid = threadIdx.x;
    for (int i = tid; i < C_ * CH48; i += 256) {
        int c = i / CH48, ch = i % CH48;
        float v;
        if (ch < 8)       v = w_theta[ch * C_ + c];
        else if (ch < 16) v = w_phi[(ch - 8) * C_ + c];
        else              v = w_g[(ch - 16) * C_ + c];
        w_s[i] = v;
    }
    if (tid < CH48) {
        bias_s[tid] = (tid < 8) ? b_theta[tid]
                    : (tid < 16 ? b_phi[tid - 8] : b_g[tid - 16]);
    }
    __syncthreads();

    int idx = blockIdx.x * 256 + tid;
    int b = idx >> 12;
    int n = idx & (N_ - 1);

    unsigned long long acc2[24];
    #pragma unroll
    for (int j = 0; j < 24; j++) acc2[j] = pack_ff(bias_s[2 * j], bias_s[2 * j + 1]);

    const float* xb = x + ((size_t)b * C_) * N_ + n;
    #pragma unroll 8
    for (int c = 0; c < C_; c++) {
        float xv = xb[(size_t)c * N_];
        unsigned long long xv2 = pack_ff(xv, xv);
        const float4* wrow = (const float4*)(w_s + c * CH48);
        #pragma unroll
        for (int j = 0; j < 12; j++) {
            float4 w4 = wrow[j];
            ffma2(acc2[2 * j],     xv2, pack_ff(w4.x, w4.y));
            ffma2(acc2[2 * j + 1], xv2, pack_ff(w4.z, w4.w));
        }
    }
    float* tb = d_tmp + ((size_t)b * CH48) * N_ + n;
    #pragma unroll
    for (int j = 0; j < 24; j++) {
        float lo, hi;
        unpack_ff(acc2[j], lo, hi);
        tb[(size_t)(2 * j) * N_]     = lo;
        tb[(size_t)(2 * j + 1) * N_] = hi;
    }
}

// ---------------------------------------------------------------------------
// P2: 2x2 maxpool (proven)
// ---------------------------------------------------------------------------
__global__ void __launch_bounds__(256) pool_kernel()
{
    int idx = blockIdx.x * 256 + threadIdx.x;
    int b  = idx / (40 * M_);
    int r  = idx % (40 * M_);
    int ch = r / M_;
    int m  = r % M_;
    int mh = m >> 5, mw = m & 31;

    const float* src = d_tmp + ((size_t)b * CH48 + 8 + ch) * N_;
    int base0 = (2 * mh) * W_ + 2 * mw;
    float2 a  = *(const float2*)(src + base0);
    float2 bb = *(const float2*)(src + base0 + W_);
    float v = fmaxf(fmaxf(a.x, a.y), fmaxf(bb.x, bb.y));

    if (ch < 8) d_phi[((size_t)b * D8 + ch) * M_ + m] = v;
    else        d_g[((size_t)b * D2 + (ch - 8)) * M_ + m] = v;
}

// ---------------------------------------------------------------------------
// Main kernel: CUDA-core fp32 logits + exp -> bf16 P in smem -> mma.sync PV
// with register-resident fp32 accumulators. One CTA = (batch, 128 queries),
// 256 threads (8 warps). Keys in 8 chunks of 128; single P buffer,
// produce -> sync -> mma -> sync per chunk.
//
// P layout: [128 q][136 bf16]  (272 B rows; 272 mod 128 = 16 -> fragment
//            loads land on 32 distinct banks)
// G layout: [32 c][1032 bf16]  (2064 B rows; same spread property)
// ---------------------------------------------------------------------------
#define PSTR 136
#define GSTR 1032
#define OFF_G    0                          // 32*2064      = 66048 B
#define OFF_P    66048                      // 128*272      = 34816 B
#define OFF_PHI  100864                     // 8*1024*4     = 32768 B
#define OFF_TH   133632                     // 128*8*4      = 4096  B
#define OFF_WO   137728                     // 64*32*4      = 8192  B
#define OFF_BO   145920                     // 64*4         = 256   B
#define OFF_AG   146176                     // 128*36*4     = 18432 B
#define SMEM_REQ 164608

__global__ void __launch_bounds__(256, 1) attn_main_kernel(
    const float* __restrict__ x,
    const float* __restrict__ w_o,
    const float* __restrict__ b_o,
    const float* __restrict__ sigma,
    float* __restrict__ out)
{
    extern __shared__ char smp[];
    float* phi_s = (float*)(smp + OFF_PHI);
    float* th_s  = (float*)(smp + OFF_TH);
    float* wo_s  = (float*)(smp + OFF_WO);
    float* bo_s  = (float*)(smp + OFF_BO);
    float* ag_s  = (float*)(smp + OFF_AG);

    int tid   = threadIdx.x;
    int warp  = tid >> 5, lane = tid & 31;
    int b     = blockIdx.y;
    int qbase = blockIdx.x * 128;

    // ---- cooperative loads ----
    {   // phi f32 (8 x 1024)
        const float4* p4 = (const float4*)(d_phi + (size_t)b * D8 * M_);
        float4* s4 = (float4*)phi_s;
        for (int i = tid; i < D8 * M_ / 4; i += 256) s4[i] = p4[i];
        // g -> bf16 [c][k] rows with padded stride
        const float* gsrc = d_g + (size_t)b * D2 * M_;
        for (int i = tid; i < D2 * (M_ / 2); i += 256) {
            int c  = i >> 9;             // 0..31
            int mp = i & 511;
            int m  = 2 * mp;
            float2 gv = *(const float2*)(gsrc + (size_t)c * M_ + m);
            __nv_bfloat162 h = __floats2bfloat162_rn(gv.x, gv.y);
            *(uint32_t*)(smp + OFF_G + c * (GSTR * 2) + m * 2) = *(uint32_t*)&h;
        }
        // theta (128 q x 8 d)
        const float* tsrc = d_tmp + (size_t)b * CH48 * N_ + qbase;
        for (int i = tid; i < 1024; i += 256) {
            int d = i >> 7, q = i & 127;
            th_s[q * 8 + d] = tsrc[(size_t)d * N_ + q];
        }
        const float4* w4 = (const float4*)w_o;
        float4* ws4 = (float4*)wo_s;
        for (int i = tid; i < 64 * 32 / 4; i += 256) ws4[i] = w4[i];
        if (tid < 64) bo_s[tid] = b_o[tid];
    }
    __syncthreads();

    int q0 = warp * 16;          // this warp's query tile (also its mma m-tile)
    int g  = lane >> 2;          // mma fragment group row
    int tg = lane & 3;           // thread-in-group

    float rs[16];                // per-warp row-sum partials (local q 0..15)
    #pragma unroll
    for (int i = 0; i < 16; i++) rs[i] = 0.f;
    float acc[4][4];             // D fragments: 4 n-tiles x 4 f32
    #pragma unroll
    for (int nt = 0; nt < 4; nt++)
        #pragma unroll
        for (int r = 0; r < 4; r++) acc[nt][r] = 0.f;

    // ---- 8 chunks of 128 keys ----
    #pragma unroll 1
    for (int ch = 0; ch < 8; ch++) {
        int mchunk = ch * 128;

        if (ch > 0) __syncthreads();   // previous chunk's mma reads done

        // -- produce P chunk: logits + exp -> bf16 --
        #pragma unroll 1
        for (int qg = 0; qg < 4; qg++) {
            int ql = qg * 4;                       // local query base
            unsigned long long th2[4][8];
            #pragma unroll
            for (int qi = 0; qi < 4; qi++)
                #pragma unroll
                for (int d = 0; d < 8; d++) {
                    float t = th_s[(q0 + ql + qi) * 8 + d];
                    th2[qi][d] = pack_ff(t, t);
                }
            #pragma unroll
            for (int j = 0; j < 2; j++) {
                int mloc = j * 64 + 2 * lane;       // within chunk
                unsigned long long s2[4] = {0ull, 0ull, 0ull, 0ull};
                #pragma unroll
                for (int d = 0; d < 8; d++) {
                    float2 p2 = *(const float2*)(phi_s + d * M_ + mchunk + mloc);
                    unsigned long long pv = pack_ff(p2.x, p2.y);
                    ffma2(s2[0], th2[0][d], pv);
                    ffma2(s2[1], th2[1][d], pv);
                    ffma2(s2[2], th2[2][d], pv);
                    ffma2(s2[3], th2[3][d], pv);
                }
                #pragma unroll
                for (int qi = 0; qi < 4; qi++) {
                    float e0, e1;
                    unpack_ff(s2[qi], e0, e1);
                    e0 = __expf(e0);                // logits bounded: exact softmax
                    e1 = __expf(e1);
                    rs[ql + qi] += e0 + e1;
                    __nv_bfloat162 h = __floats2bfloat162_rn(e0, e1);
                    *(uint32_t*)(smp + OFF_P + (q0 + ql + qi) * (PSTR * 2)
                                 + mloc * 2) = *(uint32_t*)&h;
                }
            }
        }
        __syncthreads();

        // -- consume: mma over this chunk (K = 128 -> 8 k-steps) --
        const char* Pw = smp + OFF_P + q0 * (PSTR * 2);
        const char* Gb = smp + OFF_G + (mchunk + 2 * tg) * 2;
        #pragma unroll
        for (int ks = 0; ks < 8; ks++) {
            int k0 = ks * 16;
            uint32_t a0 = *(const uint32_t*)(Pw + g * (PSTR * 2)       + (k0 + 2 * tg) * 2);
            uint32_t a1 = *(const uint32_t*)(Pw + (g + 8) * (PSTR * 2) + (k0 + 2 * tg) * 2);
            uint32_t a2 = *(const uint32_t*)(Pw + g * (PSTR * 2)       + (k0 + 8 + 2 * tg) * 2);
            uint32_t a3 = *(const uint32_t*)(Pw + (g + 8) * (PSTR * 2) + (k0 + 8 + 2 * tg) * 2);
            #pragma unroll
            for (int nt = 0; nt < 4; nt++) {
                uint32_t b0 = *(const uint32_t*)(Gb + (nt * 8 + g) * (GSTR * 2) + k0 * 2);
                uint32_t b1 = *(const uint32_t*)(Gb + (nt * 8 + g) * (GSTR * 2) + (k0 + 8) * 2);
                mma16816(acc[nt][0], acc[nt][1], acc[nt][2], acc[nt][3],
                         a0, a1, a2, a3, b0, b1);
            }
        }
    }

    // ---- row sums: xor-shuffle -> every lane holds all 16 sums ----
    #pragma unroll
    for (int qi = 0; qi < 16; qi++) {
        float v = rs[qi];
        #pragma unroll
        for (int o = 16; o; o >>= 1) v += __shfl_xor_sync(0xffffffffu, v, o);
        rs[qi] = v;
    }
    float inv_lo = 1.f / rs[g];
    float inv_hi = 1.f / rs[g + 8];

    // ---- normalize + stage AG[q][c] in smem ----
    #pragma unroll
    for (int nt = 0; nt < 4; nt++) {
        int c0 = nt * 8 + 2 * tg;
        ag_s[(q0 + g) * 36 + c0]         = acc[nt][0] * inv_lo;
        ag_s[(q0 + g) * 36 + c0 + 1]     = acc[nt][1] * inv_lo;
        ag_s[(q0 + g + 8) * 36 + c0]     = acc[nt][2] * inv_hi;
        ag_s[(q0 + g + 8) * 36 + c0 + 1] = acc[nt][3] * inv_hi;
    }
    __syncthreads();

    // ---- projection + residual epilogue (coalesced, proven) ----
    float sig = sigma[0];
    int nl = tid & 127;
    int kh = tid >> 7;

    float ag[32];
    #pragma unroll
    for (int c4 = 0; c4 < 8; c4++) {
        float4 v = *(const float4*)(ag_s + nl * 36 + 4 * c4);
        ag[4 * c4 + 0] = v.x; ag[4 * c4 + 1] = v.y;
        ag[4 * c4 + 2] = v.z; ag[4 * c4 + 3] = v.w;
    }
    size_t xoff_base = ((size_t)b * C_ + kh * 32) * N_ + qbase + nl;
    #pragma unroll 4
    for (int kk = 0; kk < 32; kk++) {
        int k = kh * 32 + kk;
        float val = bo_s[k];
        const float4* wrow = (const float4*)(wo_s + k * 32);
        #pragma unroll
        for (int c4 = 0; c4 < 8; c4++) {
            float4 w4 = wrow[c4];
            val += w4.x * ag[4 * c4] + w4.y * ag[4 * c4 + 1]
                 + w4.z * ag[4 * c4 + 2] + w4.w * ag[4 * c4 + 3];
        }
        size_t off = xoff_base + (size_t)kk * N_;
        out[off] = x[off] + sig * val;
    }
}

// ---------------------------------------------------------------------------
extern "C" void kernel_launch(void* const* d_in, const int* in_sizes, int n_in,
                              void* d_out, int out_size)
{
    const float* x       = (const float*)d_in[0];
    const float* w_theta = (const float*)d_in[1];
    const float* b_theta = (const float*)d_in[2];
    const float* w_phi   = (const float*)d_in[3];
    const float* b_phi   = (const float*)d_in[4];
    const float* w_g     = (const float*)d_in[5];
    const float* b_g     = (const float*)d_in[6];
    const float* w_o     = (const float*)d_in[7];
    const float* b_o     = (const float*)d_in[8];
    const float* sigma   = (const float*)d_in[9];
    float* out = (float*)d_out;

    conv48_kernel<<<B_ * N_ / 256, 256>>>(x, w_theta, b_theta, w_phi, b_phi, w_g, b_g);
    pool_kernel<<<B_ * 40 * M_ / 256, 256>>>();

    cudaFuncSetAttribute(attn_main_kernel,
                         cudaFuncAttributeMaxDynamicSharedMemorySize, SMEM_REQ);
    attn_main_kernel<<<dim3(N_ / 128, B_), 256, SMEM_REQ>>>(x, w_o, b_o, sigma, out);
}

// round 5
// speedup vs baseline: 2.4123x; 1.3330x over previous
#include <cuda_runtime.h>
#include <cuda_bf16.h>
#include <cstdint>

#define B_   16
#define C_   64
#define H_   64
#define W_   64
#define N_   4096
#define M_   1024
#define D8   8
#define D2   32
#define CH48 48

// Device scratch (no cudaMalloc allowed)
__device__ float d_tmp[B_ * CH48 * N_];   // theta(0..7) | phi_pre | g_pre
__device__ float d_phi[B_ * D8 * M_];     // pooled phi (f32)
__device__ float d_g[B_ * D2 * M_];       // pooled g   (f32)

// ---- f32x2 packed helpers ---------------------------------------------------
__device__ __forceinline__ void ffma2(unsigned long long& d,
                                      unsigned long long a,
                                      unsigned long long b) {
    asm("fma.rn.f32x2 %0, %1, %2, %0;" : "+l"(d) : "l"(a), "l"(b));
}
__device__ __forceinline__ unsigned long long pack_ff(float lo, float hi) {
    unsigned long long r;
    asm("mov.b64 %0, {%1,%2};" : "=l"(r) : "f"(lo), "f"(hi));
    return r;
}
__device__ __forceinline__ void unpack_ff(unsigned long long v, float& lo, float& hi) {
    asm("mov.b64 {%0,%1}, %2;" : "=f"(lo), "=f"(hi) : "l"(v));
}

// ---- mma.sync m16n8k16 bf16 (baseline PTX, legal on plain sm_103) -----------
__device__ __forceinline__ void mma16816(float& d0, float& d1, float& d2, float& d3,
                                         uint32_t a0, uint32_t a1, uint32_t a2, uint32_t a3,
                                         uint32_t b0, uint32_t b1) {
    asm volatile(
        "mma.sync.aligned.m16n8k16.row.col.f32.bf16.bf16.f32 "
        "{%0,%1,%2,%3}, {%4,%5,%6,%7}, {%8,%9}, {%0,%1,%2,%3};"
        : "+f"(d0), "+f"(d1), "+f"(d2), "+f"(d3)
        : "r"(a0), "r"(a1), "r"(a2), "r"(a3), "r"(b0), "r"(b1));
}

// ---------------------------------------------------------------------------
// P1: fused 1x1 conv, split into two 24-channel halves (512 CTAs for latency)
// ---------------------------------------------------------------------------
__global__ void __launch_bounds__(256) conv48_kernel(
    const float* __restrict__ x,
    const float* __restrict__ w_theta, const float* __restrict__ b_theta,
    const float* __restrict__ w_phi,   const float* __restrict__ b_phi,
    const float* __restrict__ w_g,     const float* __restrict__ b_g)
{
    __shared__ float w_s[C_ * 24];     // transposed: w_s[c][ch'] for this half
    __shared__ float bias_s[24];
    int tid    = threadIdx.x;
    int chbase = blockIdx.y * 24;

    for (int i = tid; i < C_ * 24; i += 256) {
        int c = i / 24, chp = i % 24;
        int ch = chbase + chp;
        float v;
        if (ch < 8)       v = w_theta[ch * C_ + c];
        else if (ch < 16) v = w_phi[(ch - 8) * C_ + c];
        else              v = w_g[(ch - 16) * C_ + c];
        w_s[i] = v;
    }
    if (tid < 24) {
        int ch = chbase + tid;
        bias_s[tid] = (ch < 8) ? b_theta[ch]
                    : (ch < 16 ? b_phi[ch - 8] : b_g[ch - 16]);
    }
    __syncthreads();

    int idx = blockIdx.x * 256 + tid;
    int b = idx >> 12;
    int n = idx & (N_ - 1);

    unsigned long long acc2[12];
    #pragma unroll
    for (int j = 0; j < 12; j++) acc2[j] = pack_ff(bias_s[2 * j], bias_s[2 * j + 1]);

    const float* xb = x + ((size_t)b * C_) * N_ + n;
    #pragma unroll 16
    for (int c = 0; c < C_; c++) {
        float xv = xb[(size_t)c * N_];
        unsigned long long xv2 = pack_ff(xv, xv);
        const float4* wrow = (const float4*)(w_s + c * 24);
        #pragma unroll
        for (int j = 0; j < 6; j++) {
            float4 w4 = wrow[j];
            ffma2(acc2[2 * j],     xv2, pack_ff(w4.x, w4.y));
            ffma2(acc2[2 * j + 1], xv2, pack_ff(w4.z, w4.w));
        }
    }
    float* tb = d_tmp + ((size_t)b * CH48 + chbase) * N_ + n;
    #pragma unroll
    for (int j = 0; j < 12; j++) {
        float lo, hi;
        unpack_ff(acc2[j], lo, hi);
        tb[(size_t)(2 * j) * N_]     = lo;
        tb[(size_t)(2 * j + 1) * N_] = hi;
    }
}

// ---------------------------------------------------------------------------
// P2: 2x2 maxpool (proven)
// ---------------------------------------------------------------------------
__global__ void __launch_bounds__(256) pool_kernel()
{
    int idx = blockIdx.x * 256 + threadIdx.x;
    int b  = idx / (40 * M_);
    int r  = idx % (40 * M_);
    int ch = r / M_;
    int m  = r % M_;
    int mh = m >> 5, mw = m & 31;

    const float* src = d_tmp + ((size_t)b * CH48 + 8 + ch) * N_;
    int base0 = (2 * mh) * W_ + 2 * mw;
    float2 a  = *(const float2*)(src + base0);
    float2 bb = *(const float2*)(src + base0 + W_);
    float v = fmaxf(fmaxf(a.x, a.y), fmaxf(bb.x, bb.y));

    if (ch < 8) d_phi[((size_t)b * D8 + ch) * M_ + m] = v;
    else        d_g[((size_t)b * D2 + (ch - 8)) * M_ + m] = v;
}

// ---------------------------------------------------------------------------
// Main kernel: 512 threads / 16 warps. Warp-pair K-split:
//   pair p = w>>1 owns queries [p*16, p*16+16); half h = w&1 handles chunks
//   2r+h (r=0..3). Each warp: produce its own bf16 P rows (private scratch)
//   -> __syncwarp -> mma.sync. NO CTA barrier in the hot loop.
// End: rowsums + fragment accumulators pair-combined through smem.
// ---------------------------------------------------------------------------
#define PSTR2 272                           // P row bytes (136 bf16)
#define PWARP 4352                          // 16 rows/warp
#define GSTR2 2064                          // G row bytes (1032 bf16)
#define XSTR  33                            // xch row stride (f32)
#define OFF_G    0                          // 32*2064   = 66048
#define OFF_P    66048                      // 16*4352   = 69632 (reused as xch)
#define OFF_PHI  135680                     // 32768
#define OFF_TH   168448                     // 4096
#define OFF_WO   172544                     // 8192
#define OFF_BO   180736                     // 256
#define OFF_AG   180992                     // 128*36*4 = 18432
#define OFF_RS   199424                     // 16*16*4  = 1024
#define SMEM_REQ 200448

__global__ void __launch_bounds__(512, 1) attn_main_kernel(
    const float* __restrict__ x,
    const float* __restrict__ w_o,
    const float* __restrict__ b_o,
    const float* __restrict__ sigma,
    float* __restrict__ out)
{
    extern __shared__ char smp[];
    float* phi_s = (float*)(smp + OFF_PHI);
    float* th_s  = (float*)(smp + OFF_TH);
    float* wo_s  = (float*)(smp + OFF_WO);
    float* bo_s  = (float*)(smp + OFF_BO);
    float* ag_s  = (float*)(smp + OFF_AG);
    float* rs_s  = (float*)(smp + OFF_RS);

    int tid   = threadIdx.x;
    int warp  = tid >> 5, lane = tid & 31;
    int b     = blockIdx.y;
    int qbase = blockIdx.x * 128;

    // ---- cooperative loads ----
    {
        const float4* p4 = (const float4*)(d_phi + (size_t)b * D8 * M_);
        float4* s4 = (float4*)phi_s;
        for (int i = tid; i < D8 * M_ / 4; i += 512) s4[i] = p4[i];
        const float* gsrc = d_g + (size_t)b * D2 * M_;
        for (int i = tid; i < D2 * (M_ / 2); i += 512) {
            int c  = i >> 9;
            int mp = i & 511;
            int m  = 2 * mp;
            float2 gv = *(const float2*)(gsrc + (size_t)c * M_ + m);
            __nv_bfloat162 h = __floats2bfloat162_rn(gv.x, gv.y);
            *(uint32_t*)(smp + OFF_G + c * GSTR2 + m * 2) = *(uint32_t*)&h;
        }
        const float* tsrc = d_tmp + (size_t)b * CH48 * N_ + qbase;
        for (int i = tid; i < 1024; i += 512) {
            int d = i >> 7, q = i & 127;
            th_s[q * 8 + d] = tsrc[(size_t)d * N_ + q];
        }
        const float4* w4 = (const float4*)w_o;
        float4* ws4 = (float4*)wo_s;
        for (int i = tid; i < 64 * 32 / 4; i += 512) ws4[i] = w4[i];
        if (tid < 64) bo_s[tid] = b_o[tid];
    }
    __syncthreads();

    int pair = warp >> 1;        // 0..7  -> query tile
    int half = warp & 1;         // 0/1   -> K half
    int q0   = pair * 16;
    int g    = lane >> 2;
    int tg   = lane & 3;
    char* Pw = smp + OFF_P + warp * PWARP;   // warp-private P scratch

    float rs[16];
    #pragma unroll
    for (int i = 0; i < 16; i++) rs[i] = 0.f;
    float acc[4][4];
    #pragma unroll
    for (int nt = 0; nt < 4; nt++)
        #pragma unroll
        for (int r = 0; r < 4; r++) acc[nt][r] = 0.f;

    // ---- 4 rounds; this warp handles chunk 2r+half ----
    #pragma unroll 1
    for (int rnd = 0; rnd < 4; rnd++) {
        int mchunk = (2 * rnd + half) * 128;

        // cache this chunk's phi in registers: [j][d], lane covers m=2*lane(+1)
        unsigned long long phi2[2][8];
        #pragma unroll
        for (int j = 0; j < 2; j++)
            #pragma unroll
            for (int d = 0; d < 8; d++) {
                float2 p2 = *(const float2*)(phi_s + d * M_ + mchunk + j * 64 + 2 * lane);
                phi2[j][d] = pack_ff(p2.x, p2.y);
            }

        // -- produce P rows (16 q), groups of 2 queries --
        #pragma unroll
        for (int qg = 0; qg < 8; qg++) {
            int ql = qg * 2;
            unsigned long long th2[2][8];
            #pragma unroll
            for (int qi = 0; qi < 2; qi++)
                #pragma unroll
                for (int d = 0; d < 8; d++) {
                    float t = th_s[(q0 + ql + qi) * 8 + d];
                    th2[qi][d] = pack_ff(t, t);
                }
            unsigned long long s2[2][2] = {{0ull, 0ull}, {0ull, 0ull}};
            #pragma unroll
            for (int d = 0; d < 8; d++) {
                ffma2(s2[0][0], th2[0][d], phi2[0][d]);
                ffma2(s2[0][1], th2[0][d], phi2[1][d]);
                ffma2(s2[1][0], th2[1][d], phi2[0][d]);
                ffma2(s2[1][1], th2[1][d], phi2[1][d]);
            }
            #pragma unroll
            for (int qi = 0; qi < 2; qi++)
                #pragma unroll
                for (int j = 0; j < 2; j++) {
                    float e0, e1;
                    unpack_ff(s2[qi][j], e0, e1);
                    e0 = __expf(e0);        // logits bounded: exact softmax
                    e1 = __expf(e1);
                    rs[ql + qi] += e0 + e1;
                    __nv_bfloat162 hh = __floats2bfloat162_rn(e0, e1);
                    *(uint32_t*)(Pw + (ql + qi) * PSTR2 + j * 128 + lane * 4)
                        = *(uint32_t*)&hh;
                }
        }
        __syncwarp();

        // -- consume: mma over this chunk (K=128 -> 8 k-steps) --
        const char* Gb = smp + OFF_G + (mchunk + 2 * tg) * 2;
        #pragma unroll
        for (int ks = 0; ks < 8; ks++) {
            int k0 = ks * 16;
            uint32_t a0 = *(const uint32_t*)(Pw + g * PSTR2       + (k0 + 2 * tg) * 2);
            uint32_t a1 = *(const uint32_t*)(Pw + (g + 8) * PSTR2 + (k0 + 2 * tg) * 2);
            uint32_t a2 = *(const uint32_t*)(Pw + g * PSTR2       + (k0 + 8 + 2 * tg) * 2);
            uint32_t a3 = *(const uint32_t*)(Pw + (g + 8) * PSTR2 + (k0 + 8 + 2 * tg) * 2);
            #pragma unroll
            for (int nt = 0; nt < 4; nt++) {
                uint32_t b0 = *(const uint32_t*)(Gb + (nt * 8 + g) * GSTR2 + k0 * 2);
                uint32_t b1 = *(const uint32_t*)(Gb + (nt * 8 + g) * GSTR2 + (k0 + 8) * 2);
                mma16816(acc[nt][0], acc[nt][1], acc[nt][2], acc[nt][3],
                         a0, a1, a2, a3, b0, b1);
            }
        }
        __syncwarp();   // P scratch reusable next round
    }

    // ---- rowsums: warp reduce, lane0 stores 16 values ----
    #pragma unroll
    for (int qi = 0; qi < 16; qi++) {
        float v = rs[qi];
        #pragma unroll
        for (int o = 16; o; o >>= 1) v += __shfl_xor_sync(0xffffffffu, v, o);
        if (lane == 0) rs_s[warp * 16 + qi] = v;
    }
    __syncthreads();    // all mma + rs done; P region reusable as exchange

    // ---- pair combine: half1 writes acc to xch; half0 adds + normalizes ----
    float* xch = (float*)(smp + OFF_P) + pair * (16 * XSTR);
    if (half == 1) {
        #pragma unroll
        for (int nt = 0; nt < 4; nt++) {
            int c0 = nt * 8 + 2 * tg;
            xch[g * XSTR + c0]           = acc[nt][0];
            xch[g * XSTR + c0 + 1]       = acc[nt][1];
            xch[(g + 8) * XSTR + c0]     = acc[nt][2];
            xch[(g + 8) * XSTR + c0 + 1] = acc[nt][3];
        }
    }
    __syncthreads();
    if (half == 0) {
        float inv_lo = 1.f / (rs_s[(2 * pair) * 16 + g]     + rs_s[(2 * pair + 1) * 16 + g]);
        float inv_hi = 1.f / (rs_s[(2 * pair) * 16 + g + 8] + rs_s[(2 * pair + 1) * 16 + g + 8]);
        #pragma unroll
        for (int nt = 0; nt < 4; nt++) {
            int c0 = nt * 8 + 2 * tg;
            ag_s[(q0 + g) * 36 + c0]         = (acc[nt][0] + xch[g * XSTR + c0])           * inv_lo;
            ag_s[(q0 + g) * 36 + c0 + 1]     = (acc[nt][1] + xch[g * XSTR + c0 + 1])       * inv_lo;
            ag_s[(q0 + g + 8) * 36 + c0]     = (acc[nt][2] + xch[(g + 8) * XSTR + c0])     * inv_hi;
            ag_s[(q0 + g + 8) * 36 + c0 + 1] = (acc[nt][3] + xch[(g + 8) * XSTR + c0 + 1]) * inv_hi;
        }
    }
    __syncthreads();

    // ---- projection + residual epilogue (coalesced) ----
    float sig = sigma[0];
    int nl = tid & 127;
    int kh = tid >> 7;       // 0..3, 16 channels each

    float ag[32];
    #pragma unroll
    for (int c4 = 0; c4 < 8; c4++) {
        float4 v = *(const float4*)(ag_s + nl * 36 + 4 * c4);
        ag[4 * c4 + 0] = v.x; ag[4 * c4 + 1] = v.y;
        ag[4 * c4 + 2] = v.z; ag[4 * c4 + 3] = v.w;
    }
    size_t xoff_base = ((size_t)b * C_ + kh * 16) * N_ + qbase + nl;
    #pragma unroll 4
    for (int kk = 0; kk < 16; kk++) {
        int k = kh * 16 + kk;
        float val = bo_s[k];
        const float4* wrow = (const float4*)(wo_s + k * 32);
        #pragma unroll
        for (int c4 = 0; c4 < 8; c4++) {
            float4 w4 = wrow[c4];
            val += w4.x * ag[4 * c4] + w4.y * ag[4 * c4 + 1]
                 + w4.z * ag[4 * c4 + 2] + w4.w * ag[4 * c4 + 3];
        }
        size_t off = xoff_base + (size_t)kk * N_;
        out[off] = x[off] + sig * val;
    }
}

// ---------------------------------------------------------------------------
extern "C" void kernel_launch(void* const* d_in, const int* in_sizes, int n_in,
                              void* d_out, int out_size)
{
    const float* x       = (const float*)d_in[0];
    const float* w_theta = (const float*)d_in[1];
    const float* b_theta = (const float*)d_in[2];
    const float* w_phi   = (const float*)d_in[3];
    const float* b_phi   = (const float*)d_in[4];
    const float* w_g     = (const float*)d_in[5];
    const float* b_g     = (const float*)d_in[6];
    const float* w_o     = (const float*)d_in[7];
    const float* b_o     = (const float*)d_in[8];
    const float* sigma   = (const float*)d_in[9];
    float* out = (float*)d_out;

    conv48_kernel<<<dim3(B_ * N_ / 256, 2), 256>>>(x, w_theta, b_theta,
                                                   w_phi, b_phi, w_g, b_g);
    pool_kernel<<<B_ * 40 * M_ / 256, 256>>>();

    cudaFuncSetAttribute(attn_main_kernel,
                         cudaFuncAttributeMaxDynamicSharedMemorySize, SMEM_REQ);
    attn_main_kernel<<<dim3(N_ / 128, B_), 512, SMEM_REQ>>>(x, w_o, b_o, sigma, out);
}

// round 6
// speedup vs baseline: 2.8422x; 1.1782x over previous
#include <cuda_runtime.h>
#include <cuda_bf16.h>
#include <cstdint>

#define B_   16
#define C_   64
#define H_   64
#define W_   64
#define N_   4096
#define M_   1024
#define D8   8
#define D2   32
#define CH48 48

// Device scratch (no cudaMalloc allowed)
__device__ float d_tmp[B_ * CH48 * N_];   // theta(0..7) | phi_pre | g_pre
__device__ float d_phi[B_ * D8 * M_];     // pooled phi (f32)
__device__ float d_g[B_ * D2 * M_];       // pooled g   (f32)

// ---- f32x2 packed helpers ---------------------------------------------------
__device__ __forceinline__ void ffma2(unsigned long long& d,
                                      unsigned long long a,
                                      unsigned long long b) {
    asm("fma.rn.f32x2 %0, %1, %2, %0;" : "+l"(d) : "l"(a), "l"(b));
}
__device__ __forceinline__ unsigned long long pack_ff(float lo, float hi) {
    unsigned long long r;
    asm("mov.b64 %0, {%1,%2};" : "=l"(r) : "f"(lo), "f"(hi));
    return r;
}
__device__ __forceinline__ void unpack_ff(unsigned long long v, float& lo, float& hi) {
    asm("mov.b64 {%0,%1}, %2;" : "=f"(lo), "=f"(hi) : "l"(v));
}

// ---- mma wrappers (baseline PTX, legal on plain sm_103) ----------------------
__device__ __forceinline__ void mma16816(float& d0, float& d1, float& d2, float& d3,
                                         uint32_t a0, uint32_t a1, uint32_t a2, uint32_t a3,
                                         uint32_t b0, uint32_t b1) {
    asm volatile(
        "mma.sync.aligned.m16n8k16.row.col.f32.bf16.bf16.f32 "
        "{%0,%1,%2,%3}, {%4,%5,%6,%7}, {%8,%9}, {%0,%1,%2,%3};"
        : "+f"(d0), "+f"(d1), "+f"(d2), "+f"(d3)
        : "r"(a0), "r"(a1), "r"(a2), "r"(a3), "r"(b0), "r"(b1));
}
__device__ __forceinline__ void mma1688_tf32(float& d0, float& d1, float& d2, float& d3,
                                             uint32_t a0, uint32_t a1, uint32_t a2, uint32_t a3,
                                             uint32_t b0, uint32_t b1) {
    asm volatile(
        "mma.sync.aligned.m16n8k8.row.col.f32.tf32.tf32.f32 "
        "{%0,%1,%2,%3}, {%4,%5,%6,%7}, {%8,%9}, {%0,%1,%2,%3};"
        : "+f"(d0), "+f"(d1), "+f"(d2), "+f"(d3)
        : "r"(a0), "r"(a1), "r"(a2), "r"(a3), "r"(b0), "r"(b1));
}
__device__ __forceinline__ uint32_t to_tf32(float v) {
    uint32_t r;
    asm("cvt.rna.tf32.f32 %0, %1;" : "=r"(r) : "f"(v));
    return r;
}
__device__ __forceinline__ uint32_t bf16x2_of(float lo, float hi) {
    uint32_t r;     // cvt.bf16x2.f32 d, a, b -> d.hi=cvt(a), d.lo=cvt(b)
    asm("cvt.rn.bf16x2.f32 %0, %1, %2;" : "=r"(r) : "f"(hi), "f"(lo));
    return r;
}

// ---------------------------------------------------------------------------
// P1: fused 1x1 conv, two 24-channel halves (proven)
// ---------------------------------------------------------------------------
__global__ void __launch_bounds__(256) conv48_kernel(
    const float* __restrict__ x,
    const float* __restrict__ w_theta, const float* __restrict__ b_theta,
    const float* __restrict__ w_phi,   const float* __restrict__ b_phi,
    const float* __restrict__ w_g,     const float* __restrict__ b_g)
{
    __shared__ float w_s[C_ * 24];
    __shared__ float bias_s[24];
    int tid    = threadIdx.x;
    int chbase = blockIdx.y * 24;

    for (int i = tid; i < C_ * 24; i += 256) {
        int c = i / 24, chp = i % 24;
        int ch = chbase + chp;
        float v;
        if (ch < 8)       v = w_theta[ch * C_ + c];
        else if (ch < 16) v = w_phi[(ch - 8) * C_ + c];
        else              v = w_g[(ch - 16) * C_ + c];
        w_s[i] = v;
    }
    if (tid < 24) {
        int ch = chbase + tid;
        bias_s[tid] = (ch < 8) ? b_theta[ch]
                    : (ch < 16 ? b_phi[ch - 8] : b_g[ch - 16]);
    }
    __syncthreads();

    int idx = blockIdx.x * 256 + tid;
    int b = idx >> 12;
    int n = idx & (N_ - 1);

    unsigned long long acc2[12];
    #pragma unroll
    for (int j = 0; j < 12; j++) acc2[j] = pack_ff(bias_s[2 * j], bias_s[2 * j + 1]);

    const float* xb = x + ((size_t)b * C_) * N_ + n;
    #pragma unroll 16
    for (int c = 0; c < C_; c++) {
        float xv = xb[(size_t)c * N_];
        unsigned long long xv2 = pack_ff(xv, xv);
        const float4* wrow = (const float4*)(w_s + c * 24);
        #pragma unroll
        for (int j = 0; j < 6; j++) {
            float4 w4 = wrow[j];
            ffma2(acc2[2 * j],     xv2, pack_ff(w4.x, w4.y));
            ffma2(acc2[2 * j + 1], xv2, pack_ff(w4.z, w4.w));
        }
    }
    float* tb = d_tmp + ((size_t)b * CH48 + chbase) * N_ + n;
    #pragma unroll
    for (int j = 0; j < 12; j++) {
        float lo, hi;
        unpack_ff(acc2[j], lo, hi);
        tb[(size_t)(2 * j) * N_]     = lo;
        tb[(size_t)(2 * j + 1) * N_] = hi;
    }
}

// ---------------------------------------------------------------------------
// P2: 2x2 maxpool (proven)
// ---------------------------------------------------------------------------
__global__ void __launch_bounds__(256) pool_kernel()
{
    int idx = blockIdx.x * 256 + threadIdx.x;
    int b  = idx / (40 * M_);
    int r  = idx % (40 * M_);
    int ch = r / M_;
    int m  = r % M_;
    int mh = m >> 5, mw = m & 31;

    const float* src = d_tmp + ((size_t)b * CH48 + 8 + ch) * N_;
    int base0 = (2 * mh) * W_ + 2 * mw;
    float2 a  = *(const float2*)(src + base0);
    float2 bb = *(const float2*)(src + base0 + W_);
    float v = fmaxf(fmaxf(a.x, a.y), fmaxf(bb.x, bb.y));

    if (ch < 8) d_phi[((size_t)b * D8 + ch) * M_ + m] = v;
    else        d_g[((size_t)b * D2 + (ch - 8)) * M_ + m] = v;
}

// ---------------------------------------------------------------------------
// Main kernel v3: full register pipeline.
//   logits  : m16n8k8 tf32 mma  (A=theta frags in regs, B=phi from smem)
//   softmax : exp of C fragments in registers (exact: no max pass, bounded)
//   PV      : C frags -> bf16x2 == A frags of m16n8k16 bf16 mma. NO P smem.
// 512 thr / 16 warps. pair=warp>>1 owns 16 queries; half=warp&1 owns 512 keys.
// phi: [d][m] f32(tf32 bits), row stride 1032 -> B-frag loads conflict-free.
// g  : [c][m] bf16, row stride 1032 bf16      -> B-frag loads conflict-free.
// ---------------------------------------------------------------------------
#define PHISTR 1032                         // f32 words per phi row
#define GSTR2  2064                         // bytes per g row (1032 bf16)
#define XSTR   33
#define OFF_G    0                          // 32*2064  = 66048
#define OFF_PHI  66048                      // 8*1032*4 = 33024 -> 99072
#define OFF_TH   99072                      // 4096  -> 103168
#define OFF_WO   103168                     // 8192  -> 111360
#define OFF_BO   111360                     // 256   -> 111616
#define OFF_AG   111616                     // 18432 -> 130048
#define OFF_RS   130048                     // 1024  -> 131072
#define OFF_XCH  131072                     // 8*16*33*4 = 16896 -> 147968
#define SMEM_REQ 147968

__global__ void __launch_bounds__(512, 1) attn_main_kernel(
    const float* __restrict__ x,
    const float* __restrict__ w_o,
    const float* __restrict__ b_o,
    const float* __restrict__ sigma,
    float* __restrict__ out)
{
    extern __shared__ char smp[];
    uint32_t* phi_s = (uint32_t*)(smp + OFF_PHI);
    uint32_t* th_s  = (uint32_t*)(smp + OFF_TH);
    float*    wo_s  = (float*)(smp + OFF_WO);
    float*    bo_s  = (float*)(smp + OFF_BO);
    float*    ag_s  = (float*)(smp + OFF_AG);
    float*    rs_s  = (float*)(smp + OFF_RS);

    int tid   = threadIdx.x;
    int warp  = tid >> 5, lane = tid & 31;
    int b     = blockIdx.y;
    int qbase = blockIdx.x * 128;

    // ---- cooperative loads ----
    {
        const float* psrc = d_phi + (size_t)b * D8 * M_;
        for (int i = tid; i < D8 * M_; i += 512) {
            int d = i >> 10, m = i & 1023;
            phi_s[d * PHISTR + m] = to_tf32(psrc[i]);
        }
        const float* gsrc = d_g + (size_t)b * D2 * M_;
        for (int i = tid; i < D2 * (M_ / 2); i += 512) {
            int c  = i >> 9;
            int m  = (i & 511) * 2;
            float2 gv = *(const float2*)(gsrc + (size_t)c * M_ + m);
            __nv_bfloat162 h = __floats2bfloat162_rn(gv.x, gv.y);
            *(uint32_t*)(smp + OFF_G + c * GSTR2 + m * 2) = *(uint32_t*)&h;
        }
        const float* tsrc = d_tmp + (size_t)b * CH48 * N_ + qbase;
        for (int i = tid; i < 1024; i += 512) {
            int d = i >> 7, q = i & 127;
            th_s[q * 8 + d] = to_tf32(tsrc[(size_t)d * N_ + q]);
        }
        const float4* w4 = (const float4*)w_o;
        float4* ws4 = (float4*)wo_s;
        for (int i = tid; i < 64 * 32 / 4; i += 512) ws4[i] = w4[i];
        if (tid < 64) bo_s[tid] = b_o[tid];
    }
    __syncthreads();

    int pair = warp >> 1;
    int half = warp & 1;
    int q0   = pair * 16;
    int g    = lane >> 2;
    int tg   = lane & 3;

    // theta A-fragments (tf32), invariant across all key units
    uint32_t ta0 = th_s[(q0 + g) * 8 + tg];
    uint32_t ta1 = th_s[(q0 + g + 8) * 8 + tg];
    uint32_t ta2 = th_s[(q0 + g) * 8 + tg + 4];
    uint32_t ta3 = th_s[(q0 + g + 8) * 8 + tg + 4];

    float rs_lo = 0.f, rs_hi = 0.f;
    float acc[4][4];
    #pragma unroll
    for (int nt = 0; nt < 4; nt++)
        #pragma unroll
        for (int r = 0; r < 4; r++) acc[nt][r] = 0.f;

    const uint32_t* phiB0 = phi_s + tg * PHISTR + g + half * 512;
    const uint32_t* phiB1 = phi_s + (tg + 4) * PHISTR + g + half * 512;
    const char*     gB    = smp + OFF_G + g * GSTR2 + (half * 512 + 2 * tg) * 2;

    // ---- 32 units of 16 keys ----
    #pragma unroll 4
    for (int u = 0; u < 32; u++) {
        int mo = u * 16;
        // logits chunk 0 (keys mo..mo+7)
        float e0 = 0.f, e1 = 0.f, e2 = 0.f, e3 = 0.f;
        mma1688_tf32(e0, e1, e2, e3, ta0, ta1, ta2, ta3, phiB0[mo], phiB1[mo]);
        // logits chunk 1 (keys mo+8..mo+15)
        float f0 = 0.f, f1 = 0.f, f2 = 0.f, f3 = 0.f;
        mma1688_tf32(f0, f1, f2, f3, ta0, ta1, ta2, ta3, phiB0[mo + 8], phiB1[mo + 8]);

        e0 = __expf(e0); e1 = __expf(e1); e2 = __expf(e2); e3 = __expf(e3);
        f0 = __expf(f0); f1 = __expf(f1); f2 = __expf(f2); f3 = __expf(f3);
        rs_lo += (e0 + e1) + (f0 + f1);
        rs_hi += (e2 + e3) + (f2 + f3);

        uint32_t a0 = bf16x2_of(e0, e1);
        uint32_t a1 = bf16x2_of(e2, e3);
        uint32_t a2 = bf16x2_of(f0, f1);
        uint32_t a3 = bf16x2_of(f2, f3);

        #pragma unroll
        for (int nt = 0; nt < 4; nt++) {
            uint32_t b0 = *(const uint32_t*)(gB + nt * (8 * GSTR2) + mo * 2);
            uint32_t b1 = *(const uint32_t*)(gB + nt * (8 * GSTR2) + (mo + 8) * 2);
            mma16816(acc[nt][0], acc[nt][1], acc[nt][2], acc[nt][3],
                     a0, a1, a2, a3, b0, b1);
        }
    }

    // ---- rowsums: reduce over quad (tg), store per-warp ----
    rs_lo += __shfl_xor_sync(0xffffffffu, rs_lo, 1);
    rs_lo += __shfl_xor_sync(0xffffffffu, rs_lo, 2);
    rs_hi += __shfl_xor_sync(0xffffffffu, rs_hi, 1);
    rs_hi += __shfl_xor_sync(0xffffffffu, rs_hi, 2);
    if (tg == 0) {
        rs_s[warp * 16 + g]     = rs_lo;
        rs_s[warp * 16 + 8 + g] = rs_hi;
    }
    __syncthreads();

    // ---- pair combine: half1 -> xch; half0 adds + normalizes into ag_s ----
    float* xch = (float*)(smp + OFF_XCH) + pair * (16 * XSTR);
    if (half == 1) {
        #pragma unroll
        for (int nt = 0; nt < 4; nt++) {
            int c0 = nt * 8 + 2 * tg;
            xch[g * XSTR + c0]           = acc[nt][0];
            xch[g * XSTR + c0 + 1]       = acc[nt][1];
            xch[(g + 8) * XSTR + c0]     = acc[nt][2];
            xch[(g + 8) * XSTR + c0 + 1] = acc[nt][3];
        }
    }
    __syncthreads();
    if (half == 0) {
        float inv_lo = 1.f / (rs_s[(2 * pair) * 16 + g]     + rs_s[(2 * pair + 1) * 16 + g]);
        float inv_hi = 1.f / (rs_s[(2 * pair) * 16 + g + 8] + rs_s[(2 * pair + 1) * 16 + g + 8]);
        #pragma unroll
        for (int nt = 0; nt < 4; nt++) {
            int c0 = nt * 8 + 2 * tg;
            ag_s[(q0 + g) * 36 + c0]         = (acc[nt][0] + xch[g * XSTR + c0])           * inv_lo;
            ag_s[(q0 + g) * 36 + c0 + 1]     = (acc[nt][1] + xch[g * XSTR + c0 + 1])       * inv_lo;
            ag_s[(q0 + g + 8) * 36 + c0]     = (acc[nt][2] + xch[(g + 8) * XSTR + c0])     * inv_hi;
            ag_s[(q0 + g + 8) * 36 + c0 + 1] = (acc[nt][3] + xch[(g + 8) * XSTR + c0 + 1]) * inv_hi;
        }
    }
    __syncthreads();

    // ---- projection + residual epilogue (coalesced, proven) ----
    float sig = sigma[0];
    int nl = tid & 127;
    int kh = tid >> 7;

    float ag[32];
    #pragma unroll
    for (int c4 = 0; c4 < 8; c4++) {
        float4 v = *(const float4*)(ag_s + nl * 36 + 4 * c4);
        ag[4 * c4 + 0] = v.x; ag[4 * c4 + 1] = v.y;
        ag[4 * c4 + 2] = v.z; ag[4 * c4 + 3] = v.w;
    }
    size_t xoff_base = ((size_t)b * C_ + kh * 16) * N_ + qbase + nl;
    #pragma unroll 4
    for (int kk = 0; kk < 16; kk++) {
        int k = kh * 16 + kk;
        float val = bo_s[k];
        const float4* wrow = (const float4*)(wo_s + k * 32);
        #pragma unroll
        for (int c4 = 0; c4 < 8; c4++) {
            float4 w4 = wrow[c4];
            val += w4.x * ag[4 * c4] + w4.y * ag[4 * c4 + 1]
                 + w4.z * ag[4 * c4 + 2] + w4.w * ag[4 * c4 + 3];
        }
        size_t off = xoff_base + (size_t)kk * N_;
        out[off] = x[off] + sig * val;
    }
}

// ---------------------------------------------------------------------------
extern "C" void kernel_launch(void* const* d_in, const int* in_sizes, int n_in,
                              void* d_out, int out_size)
{
    const float* x       = (const float*)d_in[0];
    const float* w_theta = (const float*)d_in[1];
    const float* b_theta = (const float*)d_in[2];
    const float* w_phi   = (const float*)d_in[3];
    const float* b_phi   = (const float*)d_in[4];
    const float* w_g     = (const float*)d_in[5];
    const float* b_g     = (const float*)d_in[6];
    const float* w_o     = (const float*)d_in[7];
    const float* b_o     = (const float*)d_in[8];
    const float* sigma   = (const float*)d_in[9];
    float* out = (float*)d_out;

    conv48_kernel<<<dim3(B_ * N_ / 256, 2), 256>>>(x, w_theta, b_theta,
                                                   w_phi, b_phi, w_g, b_g);
    pool_kernel<<<B_ * 40 * M_ / 256, 256>>>();

    cudaFuncSetAttribute(attn_main_kernel,
                         cudaFuncAttributeMaxDynamicSharedMemorySize, SMEM_REQ);
    attn_main_kernel<<<dim3(N_ / 128, B_), 512, SMEM_REQ>>>(x, w_o, b_o, sigma, out);
}

// round 7
// speedup vs baseline: 3.2517x; 1.1441x over previous
#include <cuda_runtime.h>
#include <cuda_bf16.h>
#include <cstdint>

#define B_   16
#define C_   64
#define H_   64
#define W_   64
#define N_   4096
#define M_   1024
#define D8   8
#define D2   32
#define CH48 48

// Device scratch (no cudaMalloc allowed)
__device__ float d_tmp[B_ * CH48 * N_];   // only theta (ch 0..7) used now
__device__ float d_phi[B_ * D8 * M_];     // pooled phi (f32)
__device__ float d_g[B_ * D2 * M_];       // pooled g   (f32)

// ---- f32x2 packed helpers ---------------------------------------------------
__device__ __forceinline__ void ffma2(unsigned long long& d,
                                      unsigned long long a,
                                      unsigned long long b) {
    asm("fma.rn.f32x2 %0, %1, %2, %0;" : "+l"(d) : "l"(a), "l"(b));
}
__device__ __forceinline__ unsigned long long pack_ff(float lo, float hi) {
    unsigned long long r;
    asm("mov.b64 %0, {%1,%2};" : "=l"(r) : "f"(lo), "f"(hi));
    return r;
}
__device__ __forceinline__ void unpack_ff(unsigned long long v, float& lo, float& hi) {
    asm("mov.b64 {%0,%1}, %2;" : "=f"(lo), "=f"(hi) : "l"(v));
}

// ---- mma wrappers (baseline PTX, legal on plain sm_103) ----------------------
__device__ __forceinline__ void mma16816(float& d0, float& d1, float& d2, float& d3,
                                         uint32_t a0, uint32_t a1, uint32_t a2, uint32_t a3,
                                         uint32_t b0, uint32_t b1) {
    asm volatile(
        "mma.sync.aligned.m16n8k16.row.col.f32.bf16.bf16.f32 "
        "{%0,%1,%2,%3}, {%4,%5,%6,%7}, {%8,%9}, {%0,%1,%2,%3};"
        : "+f"(d0), "+f"(d1), "+f"(d2), "+f"(d3)
        : "r"(a0), "r"(a1), "r"(a2), "r"(a3), "r"(b0), "r"(b1));
}
__device__ __forceinline__ void mma1688_tf32(float& d0, float& d1, float& d2, float& d3,
                                             uint32_t a0, uint32_t a1, uint32_t a2, uint32_t a3,
                                             uint32_t b0, uint32_t b1) {
    asm volatile(
        "mma.sync.aligned.m16n8k8.row.col.f32.tf32.tf32.f32 "
        "{%0,%1,%2,%3}, {%4,%5,%6,%7}, {%8,%9}, {%0,%1,%2,%3};"
        : "+f"(d0), "+f"(d1), "+f"(d2), "+f"(d3)
        : "r"(a0), "r"(a1), "r"(a2), "r"(a3), "r"(b0), "r"(b1));
}
__device__ __forceinline__ uint32_t to_tf32(float v) {
    uint32_t r;
    asm("cvt.rna.tf32.f32 %0, %1;" : "=r"(r) : "f"(v));
    return r;
}
__device__ __forceinline__ uint32_t bf16x2_of(float lo, float hi) {
    uint32_t r;
    asm("cvt.rn.bf16x2.f32 %0, %1, %2;" : "=r"(r) : "f"(hi), "f"(lo));
    return r;
}
__device__ __forceinline__ float ex2f(float v) {
    float r;
    asm("ex2.approx.f32 %0, %1;" : "=f"(r) : "f"(v));
    return r;
}

// ---------------------------------------------------------------------------
// P1: FUSED conv1x1 + 2x2 maxpool. Each thread owns one 2x2 spatial quad and
// 24 output channels (blockIdx.y selects the channel half).
//   group 0: ch 0-7  = theta (4 positions -> d_tmp), ch 8-15 = phi (max ->
//            d_phi), ch 16-23 = g0-7 (max -> d_g)
//   group 1: ch 24-47 = g8-31 (max -> d_g)
// Accumulators packed per row-pair -> every FFMA2 covers 2 positions.
// ---------------------------------------------------------------------------
__global__ void __launch_bounds__(256) convpool_kernel(
    const float* __restrict__ x,
    const float* __restrict__ w_theta, const float* __restrict__ b_theta,
    const float* __restrict__ w_phi,   const float* __restrict__ b_phi,
    const float* __restrict__ w_g,     const float* __restrict__ b_g)
{
    __shared__ float w_s[C_ * 24];     // transposed: w_s[c][chp]
    __shared__ float bias_s[24];
    int tid    = threadIdx.x;
    int chbase = blockIdx.y * 24;

    for (int i = tid; i < C_ * 24; i += 256) {
        int c = i / 24, chp = i % 24;
        int ch = chbase + chp;
        float v;
        if (ch < 8)       v = w_theta[ch * C_ + c];
        else if (ch < 16) v = w_phi[(ch - 8) * C_ + c];
        else              v = w_g[(ch - 16) * C_ + c];
        w_s[i] = v;
    }
    if (tid < 24) {
        int ch = chbase + tid;
        bias_s[tid] = (ch < 8) ? b_theta[ch]
                    : (ch < 16 ? b_phi[ch - 8] : b_g[ch - 16]);
    }
    __syncthreads();

    int idx = blockIdx.x * 256 + tid;    // quad index: B * 1024
    int b  = idx >> 10;
    int q  = idx & 1023;
    int mh = q >> 5, mw = q & 31;
    int n00 = (2 * mh) * W_ + 2 * mw;

    unsigned long long accR0[24], accR1[24];   // [chp], packed (2w, 2w+1)
    #pragma unroll
    for (int j = 0; j < 24; j++) {
        unsigned long long bb = pack_ff(bias_s[j], bias_s[j]);
        accR0[j] = bb; accR1[j] = bb;
    }

    const float* xb = x + ((size_t)b * C_) * N_ + n00;
    #pragma unroll 4
    for (int c = 0; c < C_; c++) {
        unsigned long long x0 = *(const unsigned long long*)(xb + (size_t)c * N_);
        unsigned long long x1 = *(const unsigned long long*)(xb + (size_t)c * N_ + W_);
        const float* wrow = w_s + c * 24;
        #pragma unroll
        for (int j = 0; j < 24; j++) {
            float wj = wrow[j];
            unsigned long long w2 = pack_ff(wj, wj);
            ffma2(accR0[j], x0, w2);
            ffma2(accR1[j], x1, w2);
        }
    }

    int m = mh * 32 + mw;
    if (chbase == 0) {
        // theta: store all 4 positions
        float* tb = d_tmp + (size_t)b * CH48 * N_ + n00;
        #pragma unroll
        for (int ch = 0; ch < 8; ch++) {
            *(unsigned long long*)(tb + (size_t)ch * N_)      = accR0[ch];
            *(unsigned long long*)(tb + (size_t)ch * N_ + W_) = accR1[ch];
        }
        // phi: max-pool
        #pragma unroll
        for (int ch = 8; ch < 16; ch++) {
            float a0, a1, b0, b1;
            unpack_ff(accR0[ch], a0, a1);
            unpack_ff(accR1[ch], b0, b1);
            d_phi[((size_t)b * D8 + (ch - 8)) * M_ + m]
                = fmaxf(fmaxf(a0, a1), fmaxf(b0, b1));
        }
        // g0-7: max-pool
        #pragma unroll
        for (int ch = 16; ch < 24; ch++) {
            float a0, a1, b0, b1;
            unpack_ff(accR0[ch], a0, a1);
            unpack_ff(accR1[ch], b0, b1);
            d_g[((size_t)b * D2 + (ch - 16)) * M_ + m]
                = fmaxf(fmaxf(a0, a1), fmaxf(b0, b1));
        }
    } else {
        // g8-31: max-pool
        #pragma unroll
        for (int chp = 0; chp < 24; chp++) {
            float a0, a1, b0, b1;
            unpack_ff(accR0[chp], a0, a1);
            unpack_ff(accR1[chp], b0, b1);
            d_g[((size_t)b * D2 + 8 + chp) * M_ + m]
                = fmaxf(fmaxf(a0, a1), fmaxf(b0, b1));
        }
    }
}

// ---------------------------------------------------------------------------
// Main kernel: full register pipeline (proven in R6).
//   logits  : m16n8k8 tf32 mma (theta prescaled by log2e)
//   softmax : ex2.approx on C fragments (exact math, bounded logits)
//   PV      : bf16x2 frags -> m16n8k16 bf16 mma. NO P smem.
// ---------------------------------------------------------------------------
#define PHISTR 1032
#define GSTR2  2064
#define XSTR   33
#define OFF_G    0
#define OFF_PHI  66048
#define OFF_TH   99072
#define OFF_WO   103168
#define OFF_BO   111360
#define OFF_AG   111616
#define OFF_RS   130048
#define OFF_XCH  131072
#define SMEM_REQ 147968

__global__ void __launch_bounds__(512, 1) attn_main_kernel(
    const float* __restrict__ x,
    const float* __restrict__ w_o,
    const float* __restrict__ b_o,
    const float* __restrict__ sigma,
    float* __restrict__ out)
{
    extern __shared__ char smp[];
    uint32_t* phi_s = (uint32_t*)(smp + OFF_PHI);
    uint32_t* th_s  = (uint32_t*)(smp + OFF_TH);
    float*    wo_s  = (float*)(smp + OFF_WO);
    float*    bo_s  = (float*)(smp + OFF_BO);
    float*    ag_s  = (float*)(smp + OFF_AG);
    float*    rs_s  = (float*)(smp + OFF_RS);

    int tid   = threadIdx.x;
    int warp  = tid >> 5, lane = tid & 31;
    int b     = blockIdx.y;
    int qbase = blockIdx.x * 128;

    // ---- cooperative loads ----
    {
        const float* psrc = d_phi + (size_t)b * D8 * M_;
        for (int i = tid; i < D8 * M_; i += 512) {
            int d = i >> 10, m = i & 1023;
            phi_s[d * PHISTR + m] = to_tf32(psrc[i]);
        }
        const float* gsrc = d_g + (size_t)b * D2 * M_;
        for (int i = tid; i < D2 * (M_ / 2); i += 512) {
            int c  = i >> 9;
            int m  = (i & 511) * 2;
            float2 gv = *(const float2*)(gsrc + (size_t)c * M_ + m);
            __nv_bfloat162 h = __floats2bfloat162_rn(gv.x, gv.y);
            *(uint32_t*)(smp + OFF_G + c * GSTR2 + m * 2) = *(uint32_t*)&h;
        }
        const float* tsrc = d_tmp + (size_t)b * CH48 * N_ + qbase;
        for (int i = tid; i < 1024; i += 512) {
            int d = i >> 7, q = i & 127;
            th_s[q * 8 + d] = to_tf32(tsrc[(size_t)d * N_ + q] * 1.4426950408889634f);
        }
        const float4* w4 = (const float4*)w_o;
        float4* ws4 = (float4*)wo_s;
        for (int i = tid; i < 64 * 32 / 4; i += 512) ws4[i] = w4[i];
        if (tid < 64) bo_s[tid] = b_o[tid];
    }
    __syncthreads();

    int pair = warp >> 1;
    int half = warp & 1;
    int q0   = pair * 16;
    int g    = lane >> 2;
    int tg   = lane & 3;

    uint32_t ta0 = th_s[(q0 + g) * 8 + tg];
    uint32_t ta1 = th_s[(q0 + g + 8) * 8 + tg];
    uint32_t ta2 = th_s[(q0 + g) * 8 + tg + 4];
    uint32_t ta3 = th_s[(q0 + g + 8) * 8 + tg + 4];

    float rs_lo = 0.f, rs_hi = 0.f;
    float acc[4][4];
    #pragma unroll
    for (int nt = 0; nt < 4; nt++)
        #pragma unroll
        for (int r = 0; r < 4; r++) acc[nt][r] = 0.f;

    const uint32_t* phiB0 = phi_s + tg * PHISTR + g + half * 512;
    const uint32_t* phiB1 = phi_s + (tg + 4) * PHISTR + g + half * 512;
    const char*     gB    = smp + OFF_G + g * GSTR2 + (half * 512 + 2 * tg) * 2;

    // ---- 32 units of 16 keys ----
    #pragma unroll 4
    for (int u = 0; u < 32; u++) {
        int mo = u * 16;
        float e0 = 0.f, e1 = 0.f, e2 = 0.f, e3 = 0.f;
        mma1688_tf32(e0, e1, e2, e3, ta0, ta1, ta2, ta3, phiB0[mo], phiB1[mo]);
        float f0 = 0.f, f1 = 0.f, f2 = 0.f, f3 = 0.f;
        mma1688_tf32(f0, f1, f2, f3, ta0, ta1, ta2, ta3, phiB0[mo + 8], phiB1[mo + 8]);

        e0 = ex2f(e0); e1 = ex2f(e1); e2 = ex2f(e2); e3 = ex2f(e3);
        f0 = ex2f(f0); f1 = ex2f(f1); f2 = ex2f(f2); f3 = ex2f(f3);
        rs_lo += (e0 + e1) + (f0 + f1);
        rs_hi += (e2 + e3) + (f2 + f3);

        uint32_t a0 = bf16x2_of(e0, e1);
        uint32_t a1 = bf16x2_of(e2, e3);
        uint32_t a2 = bf16x2_of(f0, f1);
        uint32_t a3 = bf16x2_of(f2, f3);

        #pragma unroll
        for (int nt = 0; nt < 4; nt++) {
            uint32_t b0 = *(const uint32_t*)(gB + nt * (8 * GSTR2) + mo * 2);
            uint32_t b1 = *(const uint32_t*)(gB + nt * (8 * GSTR2) + (mo + 8) * 2);
            mma16816(acc[nt][0], acc[nt][1], acc[nt][2], acc[nt][3],
                     a0, a1, a2, a3, b0, b1);
        }
    }

    // ---- rowsums over quad ----
    rs_lo += __shfl_xor_sync(0xffffffffu, rs_lo, 1);
    rs_lo += __shfl_xor_sync(0xffffffffu, rs_lo, 2);
    rs_hi += __shfl_xor_sync(0xffffffffu, rs_hi, 1);
    rs_hi += __shfl_xor_sync(0xffffffffu, rs_hi, 2);
    if (tg == 0) {
        rs_s[warp * 16 + g]     = rs_lo;
        rs_s[warp * 16 + 8 + g] = rs_hi;
    }
    __syncthreads();

    // ---- pair combine ----
    float* xch = (float*)(smp + OFF_XCH) + pair * (16 * XSTR);
    if (half == 1) {
        #pragma unroll
        for (int nt = 0; nt < 4; nt++) {
            int c0 = nt * 8 + 2 * tg;
            xch[g * XSTR + c0]           = acc[nt][0];
            xch[g * XSTR + c0 + 1]       = acc[nt][1];
            xch[(g + 8) * XSTR + c0]     = acc[nt][2];
            xch[(g + 8) * XSTR + c0 + 1] = acc[nt][3];
        }
    }
    __syncthreads();
    if (half == 0) {
        float inv_lo = 1.f / (rs_s[(2 * pair) * 16 + g]     + rs_s[(2 * pair + 1) * 16 + g]);
        float inv_hi = 1.f / (rs_s[(2 * pair) * 16 + g + 8] + rs_s[(2 * pair + 1) * 16 + g + 8]);
        #pragma unroll
        for (int nt = 0; nt < 4; nt++) {
            int c0 = nt * 8 + 2 * tg;
            ag_s[(q0 + g) * 36 + c0]         = (acc[nt][0] + xch[g * XSTR + c0])           * inv_lo;
            ag_s[(q0 + g) * 36 + c0 + 1]     = (acc[nt][1] + xch[g * XSTR + c0 + 1])       * inv_lo;
            ag_s[(q0 + g + 8) * 36 + c0]     = (acc[nt][2] + xch[(g + 8) * XSTR + c0])     * inv_hi;
            ag_s[(q0 + g + 8) * 36 + c0 + 1] = (acc[nt][3] + xch[(g + 8) * XSTR + c0 + 1]) * inv_hi;
        }
    }
    __syncthreads();

    // ---- projection + residual epilogue ----
    float sig = sigma[0];
    int nl = tid & 127;
    int kh = tid >> 7;

    float ag[32];
    #pragma unroll
    for (int c4 = 0; c4 < 8; c4++) {
        float4 v = *(const float4*)(ag_s + nl * 36 + 4 * c4);
        ag[4 * c4 + 0] = v.x; ag[4 * c4 + 1] = v.y;
        ag[4 * c4 + 2] = v.z; ag[4 * c4 + 3] = v.w;
    }
    size_t xoff_base = ((size_t)b * C_ + kh * 16) * N_ + qbase + nl;
    #pragma unroll 4
    for (int kk = 0; kk < 16; kk++) {
        int k = kh * 16 + kk;
        float val = bo_s[k];
        const float4* wrow = (const float4*)(wo_s + k * 32);
        #pragma unroll
        for (int c4 = 0; c4 < 8; c4++) {
            float4 w4 = wrow[c4];
            val += w4.x * ag[4 * c4] + w4.y * ag[4 * c4 + 1]
                 + w4.z * ag[4 * c4 + 2] + w4.w * ag[4 * c4 + 3];
        }
        size_t off = xoff_base + (size_t)kk * N_;
        out[off] = x[off] + sig * val;
    }
}

// ---------------------------------------------------------------------------
extern "C" void kernel_launch(void* const* d_in, const int* in_sizes, int n_in,
                              void* d_out, int out_size)
{
    const float* x       = (const float*)d_in[0];
    const float* w_theta = (const float*)d_in[1];
    const float* b_theta = (const float*)d_in[2];
    const float* w_phi   = (const float*)d_in[3];
    const float* b_phi   = (const float*)d_in[4];
    const float* w_g     = (const float*)d_in[5];
    const float* b_g     = (const float*)d_in[6];
    const float* w_o     = (const float*)d_in[7];
    const float* b_o     = (const float*)d_in[8];
    const float* sigma   = (const float*)d_in[9];
    float* out = (float*)d_out;

    convpool_kernel<<<dim3(B_ * 1024 / 256, 2), 256>>>(x, w_theta, b_theta,
                                                       w_phi, b_phi, w_g, b_g);

    cudaFuncSetAttribute(attn_main_kernel,
                         cudaFuncAttributeMaxDynamicSharedMemorySize, SMEM_REQ);
    attn_main_kernel<<<dim3(N_ / 128, B_), 512, SMEM_REQ>>>(x, w_o, b_o, sigma, out);
}